// round 9
// baseline (speedup 1.0000x reference)
#include <cuda_runtime.h>
#include <math.h>
#include <stdint.h>

#define NUM_LEVEL 16
#define N_POINTS  262144
#define TOTAL     (N_POINTS * NUM_LEVEL)   // 4,194,304 (point,level) items

#define NUM_CTAS   1184                    // 148 SMs x 8 resident CTAs -> 1 wave
#define BLOCK_SIZE 256

struct LevelMeta {
    float    scale;
    uint32_t res;
    uint32_t offset;   // in float2 entries
    uint32_t mask;     // hsize-1 (hashed levels: hsize = 2^19)
    uint32_t hashed;
    uint32_t pad;
};

struct Meta {
    LevelMeta lv[NUM_LEVEL];
};

// Persistent grid-stride kernel: exactly one wave of CTAs, no wave-transition
// overhead. Body identical to the best-known R8 configuration.
__global__ void __launch_bounds__(BLOCK_SIZE)
grid_encode_kernel(const float* __restrict__ pts,
                   const float2* __restrict__ emb,
                   float2* __restrict__ out,
                   Meta meta)
{
    const uint32_t stride = NUM_CTAS * BLOCK_SIZE;   // 303,104

    for (uint32_t tid = blockIdx.x * BLOCK_SIZE + threadIdx.x;
         tid < (uint32_t)TOTAL; tid += stride)
    {
        const uint32_t n = tid >> 4;     // point index
        const uint32_t l = tid & 15;     // level index

        // 16 consecutive threads share one point: L1 broadcast
        const float inx = __ldg(pts + n * 3 + 0);
        const float iny = __ldg(pts + n * 3 + 1);
        const float inz = __ldg(pts + n * 3 + 2);

        const LevelMeta m = meta.lv[l];

        const float px = (inx + 1.0f) * 0.5f * m.scale;
        const float py = (iny + 1.0f) * 0.5f * m.scale;
        const float pz = (inz + 1.0f) * 0.5f * m.scale;

        const float gx = floorf(px), gy = floorf(py), gz = floorf(pz);
        const float fx = px - gx,   fy = py - gy,   fz = pz - gz;

        const uint32_t ix = (uint32_t)gx;
        const uint32_t iy = (uint32_t)gy;
        const uint32_t iz = (uint32_t)gz;

        const float wx[2] = {1.0f - fx, fx};
        const float wy[2] = {1.0f - fy, fy};
        const float wz[2] = {1.0f - fz, fz};

        const float2* __restrict__ table = emb + m.offset;
        const uint32_t r      = m.res;
        const uint32_t r2     = r * r;
        const uint32_t mask   = m.mask;
        const bool     hashed = (m.hashed != 0u);

        float accx = 0.0f, accy = 0.0f;

        #pragma unroll
        for (int c = 0; c < 8; ++c) {
            const uint32_t bx = (uint32_t)(c & 1);
            const uint32_t by = (uint32_t)((c >> 1) & 1);
            const uint32_t bz = (uint32_t)(c >> 2);
            const uint32_t cx = ix + bx;
            const uint32_t cy = iy + by;
            const uint32_t cz = iz + bz;

            const uint32_t hidx = (cx ^ (cy * 2654435761u) ^ (cz * 805459861u)) & mask;
            const uint32_t didx = cx + cy * r + cz * r2;   // < hsize by construction
            const uint32_t idx  = hashed ? hidx : didx;    // SEL, no branch

            const float w = wx[bx] * wy[by] * wz[bz];
            const float2 f = __ldg(table + idx);
            accx = fmaf(w, f.x, accx);
            accy = fmaf(w, f.y, accy);
        }

        // Write-once output: streaming store (evict-first)
        __stcs(out + n * (uint32_t)NUM_LEVEL + l, make_float2(accx, accy));
    }
}

// Host-side meta, bit-matching the reference's double-precision math.
static void compute_meta(Meta& M)
{
    const double ls = 1.38191288;
    const double lg = log2(ls);
    uint32_t off = 0;
    for (int i = 0; i < NUM_LEVEL; ++i) {
        double s   = exp2((double)i * lg) * 16.0 - 1.0;
        int    res = (int)ceil(s) + 1;

        double   res_meta = ceil(16.0 * pow(ls, (double)i));
        double   p3 = res_meta * res_meta * res_meta;
        uint32_t p  = (p3 > 524288.0) ? 524288u : (uint32_t)p3;
        p = ((p + 7u) / 8u) * 8u;

        unsigned long long res3 =
            (unsigned long long)res * (unsigned long long)res * (unsigned long long)res;
        bool hashed = res3 > (unsigned long long)p;

        M.lv[i].scale  = (float)s;
        M.lv[i].res    = (uint32_t)res;
        M.lv[i].offset = off;
        M.lv[i].mask   = p - 1u;
        M.lv[i].hashed = hashed ? 1u : 0u;
        M.lv[i].pad    = 0;

        off += p;
    }
}

extern "C" void kernel_launch(void* const* d_in, const int* in_sizes, int n_in,
                              void* d_out, int out_size)
{
    const float*  pts = (const float*)d_in[0];   // [N_POINTS, 3]
    const float2* emb = (const float2*)d_in[1];  // [offs[-1], 2]
    float2*       out = (float2*)d_out;          // [N_POINTS, 16] float2

    Meta M;
    compute_meta(M);

    grid_encode_kernel<<<NUM_CTAS, BLOCK_SIZE>>>(pts, emb, out, M);
}

// round 11
// speedup vs baseline: 1.0736x; 1.0736x over previous
#include <cuda_runtime.h>
#include <math.h>
#include <stdint.h>

#define NUM_LEVEL 16
#define N_POINTS  262144

struct LevelMeta {
    float    scale;
    uint32_t res;
    uint32_t offset;   // in float2 entries (multiple of 8 -> 64B aligned)
    uint32_t mask;     // hsize-1 (hashed levels: hsize = 2^19)
    uint32_t hashed;
    uint32_t pad;
};

struct Meta {
    LevelMeta lv[NUM_LEVEL];
};

__global__ void __launch_bounds__(256)
grid_encode_kernel(const float* __restrict__ pts,
                   const float2* __restrict__ emb,
                   float2* __restrict__ out,
                   Meta meta)
{
    const uint32_t tid = blockIdx.x * blockDim.x + threadIdx.x;

    const uint32_t n = tid >> 4;     // point index
    const uint32_t l = tid & 15;     // level index

    // 16 consecutive threads share one point: L1 broadcast
    const float inx = __ldg(pts + n * 3 + 0);
    const float iny = __ldg(pts + n * 3 + 1);
    const float inz = __ldg(pts + n * 3 + 2);

    const LevelMeta m = meta.lv[l];

    const float px = (inx + 1.0f) * 0.5f * m.scale;
    const float py = (iny + 1.0f) * 0.5f * m.scale;
    const float pz = (inz + 1.0f) * 0.5f * m.scale;

    const float gx = floorf(px), gy = floorf(py), gz = floorf(pz);
    const float fx = px - gx,   fy = py - gy,   fz = pz - gz;

    const uint32_t ix = (uint32_t)gx;
    const uint32_t iy = (uint32_t)gy;
    const uint32_t iz = (uint32_t)gz;

    const float wx0 = 1.0f - fx, wx1 = fx;
    const float wy[2] = {1.0f - fy, fy};
    const float wz[2] = {1.0f - fz, fz};

    float accx = 0.0f, accy = 0.0f;

    if (m.hashed) {
        // Hashed level (hsize = 2^19, x-prime = 1). The table entry for corner
        // x is (x ^ t) & mask. When ix is EVEN, corners ix and ix+1 differ only
        // in bit0 -> both live in one aligned float4. The parity test is
        // thread-uniform (ix & 1). All hashed loads use .cg so the random
        // stream doesn't evict the dense tables from L1; pair locality is
        // captured inside the single LDG.128 instead of relying on L1.
        const float2* __restrict__ table = emb + m.offset;
        const float4* __restrict__ tab4  = (const float4*)(emb + m.offset);
        const uint32_t mask  = m.mask;
        const bool     ixodd = (ix & 1u) != 0u;

        #pragma unroll
        for (int p = 0; p < 4; ++p) {
            const uint32_t by = (uint32_t)(p & 1);
            const uint32_t bz = (uint32_t)(p >> 1);
            const uint32_t t  = ((iy + by) * 2654435761u) ^ ((iz + bz) * 805459861u);

            const uint32_t idxA = (ix ^ t) & mask;       // entry of corner bx=0
            const bool     odd  = (idxA & 1u) != 0u;     // which half of the float4

            const float4 f4 = __ldcg(tab4 + (idxA >> 1));

            // corner bx=0 is in this block, half selected by bit0
            const float2 cA = odd ? make_float2(f4.z, f4.w)
                                  : make_float2(f4.x, f4.y);
            // corner bx=1: same block's other half iff ix even, else a
            // separate gather (predicated; thread-uniform condition)
            float2 cB;
            if (!ixodd) {
                cB = odd ? make_float2(f4.x, f4.y)
                         : make_float2(f4.z, f4.w);
            } else {
                cB = __ldcg(table + (((ix + 1u) ^ t) & mask));
            }

            const float wyz = wy[by] * wz[bz];
            const float wA  = wx0 * wyz;
            const float wB  = wx1 * wyz;

            accx = fmaf(wA, cA.x, accx);
            accy = fmaf(wA, cA.y, accy);
            accx = fmaf(wB, cB.x, accx);
            accy = fmaf(wB, cB.y, accy);
        }
    } else {
        // Dense level: proven R8 path, 8 interleaved L1-allocating LDG.64 + FMA.
        // Small tables (32KB..1.6MB) now protected from hash-stream thrash.
        const float2* __restrict__ table = emb + m.offset;
        const uint32_t r  = m.res;
        const uint32_t r2 = r * r;
        const float wxp[2] = {wx0, wx1};

        #pragma unroll
        for (int c = 0; c < 8; ++c) {
            const uint32_t bx = (uint32_t)(c & 1);
            const uint32_t by = (uint32_t)((c >> 1) & 1);
            const uint32_t bz = (uint32_t)(c >> 2);
            const uint32_t idx = (ix + bx) + (iy + by) * r + (iz + bz) * r2;

            const float w = wxp[bx] * wy[by] * wz[bz];
            const float2 f = __ldg(table + idx);
            accx = fmaf(w, f.x, accx);
            accy = fmaf(w, f.y, accy);
        }
    }

    // Write-once output: streaming store (evict-first)
    __stcs(out + n * (uint32_t)NUM_LEVEL + l, make_float2(accx, accy));
}

// Host-side meta, bit-matching the reference's double-precision math.
static void compute_meta(Meta& M)
{
    const double ls = 1.38191288;
    const double lg = log2(ls);
    uint32_t off = 0;
    for (int i = 0; i < NUM_LEVEL; ++i) {
        double s   = exp2((double)i * lg) * 16.0 - 1.0;
        int    res = (int)ceil(s) + 1;

        double   res_meta = ceil(16.0 * pow(ls, (double)i));
        double   p3 = res_meta * res_meta * res_meta;
        uint32_t p  = (p3 > 524288.0) ? 524288u : (uint32_t)p3;
        p = ((p + 7u) / 8u) * 8u;

        unsigned long long res3 =
            (unsigned long long)res * (unsigned long long)res * (unsigned long long)res;
        bool hashed = res3 > (unsigned long long)p;

        M.lv[i].scale  = (float)s;
        M.lv[i].res    = (uint32_t)res;
        M.lv[i].offset = off;
        M.lv[i].mask   = p - 1u;
        M.lv[i].hashed = hashed ? 1u : 0u;
        M.lv[i].pad    = 0;

        off += p;
    }
}

extern "C" void kernel_launch(void* const* d_in, const int* in_sizes, int n_in,
                              void* d_out, int out_size)
{
    const float*  pts = (const float*)d_in[0];   // [N_POINTS, 3]
    const float2* emb = (const float2*)d_in[1];  // [offs[-1], 2]
    float2*       out = (float2*)d_out;          // [N_POINTS, 16] float2

    Meta M;
    compute_meta(M);

    const uint32_t total   = (uint32_t)N_POINTS * NUM_LEVEL;  // 4,194,304
    const uint32_t threads = 256;
    const uint32_t blocks  = total / threads;                 // exact

    grid_encode_kernel<<<blocks, threads>>>(pts, emb, out, M);
}